// round 10
// baseline (speedup 1.0000x reference)
#include <cuda_runtime.h>
#include <math.h>
#include <stdint.h>

#define NN 100000
#define NE 1600000
#define KTOT 168          // z-GEMM K padded 161 -> 168
#define KPAD 172          // z-GEMM A smem stride
#define KP2 132           // head A smem stride
#define HD 100            // head result smem stride

// ---------------- scratch (device globals: allocation-free) ----------------
__device__ __align__(16) float g_zf[NN * 64];
__device__ __align__(16) float g_zb[NN * 64];
__device__ __align__(16) float g_acc[NN * 64];
__device__ float g_degf[NN];
__device__ float g_degb[NN];
__device__ __align__(16) float g_Wk[KTOT * 128]; // folded z weights (tf32), [k][c]
__device__ __align__(16) float g_bz[128];
__device__ __align__(16) float g_Wh[128 * 96];   // head weights [k][mu|sig|pi] (tf32)

// ---------------- helpers ----------------
__device__ __forceinline__ unsigned f2tf32(float v) {
    unsigned o; asm("cvt.rna.tf32.f32 %0, %1;" : "=r"(o) : "f"(v)); return o;
}

__device__ __forceinline__ void mma_tf32(float* d,
                                         unsigned a0, unsigned a1, unsigned a2, unsigned a3,
                                         unsigned b0, unsigned b1) {
    asm volatile("mma.sync.aligned.m16n8k8.row.col.f32.tf32.tf32.f32 "
                 "{%0,%1,%2,%3}, {%4,%5,%6,%7}, {%8,%9}, {%0,%1,%2,%3};"
                 : "+f"(d[0]), "+f"(d[1]), "+f"(d[2]), "+f"(d[3])
                 : "r"(a0), "r"(a1), "r"(a2), "r"(a3), "r"(b0), "r"(b1));
}

// ---------------- init accumulator + degrees ----------------
__global__ void k_init() {
    int i = blockIdx.x * blockDim.x + threadIdx.x;
    int st = gridDim.x * blockDim.x;
    float4 z = make_float4(0.f, 0.f, 0.f, 0.f);
    for (int j = i; j < NN * 16; j += st)
        reinterpret_cast<float4*>(g_acc)[j] = z;
    for (int j = i; j < NN; j += st) { g_degf[j] = 0.f; g_degb[j] = 0.f; }
}

// ---------------- fold W_filt into W_in (k-major, tf32) ----------------
__global__ void k_wfold(const float* __restrict__ Win, const float* __restrict__ bin,
                        const float* __restrict__ Wf) {
    __shared__ float wsel[64];
    int c = blockIdx.x;                 // 0..127
    if (threadIdx.x < 64) {
        int j = threadIdx.x;
        wsel[j] = (c < 64) ? Wf[j * 64 + c] : Wf[(64 + j) * 64 + (c - 64)];
    }
    __syncthreads();
    int k = threadIdx.x;
    if (k < KTOT) {
        float a = 0.f;
        if (k < 161) {
#pragma unroll 8
            for (int j = 0; j < 64; j++) a += Win[k * 64 + j] * wsel[j];
        }
        g_Wk[k * 128 + c] = __uint_as_float(f2tf32(a));
    }
    if (threadIdx.x == 0) {
        float b = 0.f;
        for (int j = 0; j < 64; j++) b += bin[j] * wsel[j];
        g_bz[c] = b;
    }
}

// ---------------- pack head weights [Wm|Ws|Wp] -> g_Wh[k][96] (tf32) ----------------
__global__ void k_whead(const float* __restrict__ Wm, const float* __restrict__ Wsg,
                        const float* __restrict__ Wp) {
    int c = blockIdx.x;                 // 0..95
    int j = threadIdx.x;                // 0..127
    float v = (c < 32) ? Wm[j * 32 + c]
            : (c < 64) ? Wsg[j * 32 + (c - 32)]
                       : Wp[j * 32 + (c - 64)];
    g_Wh[j * 96 + c] = __uint_as_float(f2tf32(v));
}

// ---------------- weighted degrees ----------------
__global__ void k_deg(const int* __restrict__ ei, const float* __restrict__ ew) {
    int e = blockIdx.x * blockDim.x + threadIdx.x;
    if (e >= NE) return;
    int s = ei[e], t = ei[NE + e];
    float w = ew[e];
    if (s != t) {
        atomicAdd(&g_degf[t], w);
        atomicAdd(&g_degb[s], w);
    }
}

// ---------------- z = A @ Wc + bz  (tf32 MMA) ----------------
#define Z_SMEM (128 * KPAD * 4)

__global__ __launch_bounds__(256) void k_z(const float* __restrict__ x,
                                           const float* __restrict__ xh,
                                           const float* __restrict__ hh) {
    extern __shared__ float As[];       // [128][KPAD]
    const int tid = threadIdx.x;
    const int base = blockIdx.x * 128;

    for (int i = tid; i < 128 * KPAD / 4; i += 256)
        reinterpret_cast<float4*>(As)[i] = make_float4(0.f, 0.f, 0.f, 0.f);
    __syncthreads();

    {
        int lim = min(128, NN - base);
        if (tid < lim) As[tid * KPAD] = __uint_as_float(f2tf32(x[base + tid]));
        for (int i = tid; i < lim * 96; i += 256) {
            int m = i / 96, k = i - m * 96;
            As[m * KPAD + 1 + k] = __uint_as_float(f2tf32(xh[(size_t)(base + m) * 96 + k]));
        }
        for (int i = tid; i < lim * 64; i += 256) {
            int m = i >> 6, k = i & 63;
            As[m * KPAD + 97 + k] = __uint_as_float(f2tf32(hh[(size_t)(base + m) * 64 + k]));
        }
    }
    __syncthreads();

    const int lane = tid & 31;
    const int w    = tid >> 5;
    const int wm = (w >> 2) * 64;
    const int wn = (w & 3) * 32;
    const int g = lane >> 2, t = lane & 3;
    const unsigned* Au = reinterpret_cast<const unsigned*>(As);

    float acc[4][4][4];
#pragma unroll
    for (int mf = 0; mf < 4; mf++)
#pragma unroll
        for (int nf = 0; nf < 4; nf++)
#pragma unroll
            for (int q = 0; q < 4; q++) acc[mf][nf][q] = 0.f;

#pragma unroll 1
    for (int ks = 0; ks < 21; ks++) {
        const int k0 = ks * 8;
        unsigned bfr[4][2];
#pragma unroll
        for (int nf = 0; nf < 4; nf++) {
            int nc = wn + nf * 8 + g;
            bfr[nf][0] = __float_as_uint(__ldg(&g_Wk[(k0 + t) * 128 + nc]));
            bfr[nf][1] = __float_as_uint(__ldg(&g_Wk[(k0 + 4 + t) * 128 + nc]));
        }
#pragma unroll
        for (int mf = 0; mf < 4; mf++) {
            int r0 = wm + mf * 16 + g;
            unsigned a0 = Au[r0 * KPAD + k0 + t];
            unsigned a1 = Au[(r0 + 8) * KPAD + k0 + t];
            unsigned a2 = Au[r0 * KPAD + k0 + 4 + t];
            unsigned a3 = Au[(r0 + 8) * KPAD + k0 + 4 + t];
#pragma unroll
            for (int nf = 0; nf < 4; nf++)
                mma_tf32(acc[mf][nf], a0, a1, a2, a3, bfr[nf][0], bfr[nf][1]);
        }
    }

#pragma unroll
    for (int nf = 0; nf < 4; nf++) {
        int c = wn + nf * 8 + 2 * t;
        float bi0 = g_bz[c], bi1 = g_bz[c + 1];
        float* dst = (c < 64) ? g_zf : g_zb;
        int cd = (c < 64) ? c : c - 64;
#pragma unroll
        for (int mf = 0; mf < 4; mf++) {
            int m0 = base + wm + mf * 16 + g;
            if (m0 < NN)
                *reinterpret_cast<float2*>(&dst[(size_t)m0 * 64 + cd]) =
                    make_float2(acc[mf][nf][0] + bi0, acc[mf][nf][1] + bi1);
            int m1 = m0 + 8;
            if (m1 < NN)
                *reinterpret_cast<float2*>(&dst[(size_t)m1 * 64 + cd]) =
                    make_float2(acc[mf][nf][2] + bi0, acc[mf][nf][3] + bi1);
        }
    }
}

// ---------------- scatter (inline weights, lead-lane + shfl) ----------------
__device__ __forceinline__ void red4(float* p, float a, float b, float c, float d) {
    asm volatile("red.global.add.v4.f32 [%0], {%1, %2, %3, %4};"
                 :: "l"(p), "f"(a), "f"(b), "f"(c), "f"(d) : "memory");
}

__global__ __launch_bounds__(256) void k_scatter(const int* __restrict__ ei,
                                                 const float* __restrict__ ew) {
    const int lane = threadIdx.x & 31;
    const int sub  = lane & 15;          // position within 16-lane edge group
    const unsigned warp_id = blockIdx.x * 8u + (threadIdx.x >> 5);
    const unsigned e = warp_id * 2u + (unsigned)(lane >> 4);
    if (e >= NE) return;                 // grid covers NE exactly, kept for safety

    int s = 0, t = 0;
    float wf = 0.f, wb = 0.f;
    if (sub == 0) {                      // lanes 0 and 16 do the scalar work
        s = __ldg(&ei[e]);
        t = __ldg(&ei[NE + e]);
        float w = __ldg(&ew[e]);
        if (s == t) w = 0.f;
        float df = __ldg(&g_degf[t]);
        float db = __ldg(&g_degb[s]);
        wf = (df > 0.f) ? w / df : 0.f;
        wb = (db > 0.f) ? w / db : 0.f;
    }
    const int srcl = lane & 16;          // broadcast source within each half
    s  = __shfl_sync(0xFFFFFFFFu, s,  srcl);
    t  = __shfl_sync(0xFFFFFFFFu, t,  srcl);
    wf = __shfl_sync(0xFFFFFFFFu, wf, srcl);
    wb = __shfl_sync(0xFFFFFFFFu, wb, srcl);

    float4 vs = *reinterpret_cast<const float4*>(g_zf + (size_t)s * 64 + 4 * sub);
    red4(g_acc + (size_t)t * 64 + 4 * sub, wf * vs.x, wf * vs.y, wf * vs.z, wf * vs.w);
    float4 vt = *reinterpret_cast<const float4*>(g_zb + (size_t)t * 64 + 4 * sub);
    red4(g_acc + (size_t)s * 64 + 4 * sub, wb * vt.x, wb * vt.y, wb * vt.z, wb * vt.w);
}

// ---------------- head: tf32 MMA GMM heads + outputs ----------------
#define HEAD_SMEM (128 * KP2 * 4)

__global__ __launch_bounds__(256) void k_head(const float* __restrict__ hh,
                                              const float* __restrict__ bf,
                                              const float* __restrict__ bm,
                                              const float* __restrict__ bsg,
                                              const float* __restrict__ bp,
                                              float* __restrict__ out, int write_extra) {
    extern __shared__ float sms[];
    float* As = sms;                     // [128][KP2], later aliased as hd [128][HD]
    float* hd = sms;

    const int tid = threadIdx.x;
    const int base = blockIdx.x * 128;
    const int lim = min(128, NN - base);

    float* ogmm = out;
    float* oo1  = out + (size_t)NN * 96;
    float* oh   = out + (size_t)NN * 96 + (size_t)NN * 128;

    for (int i = tid; i < 128 * KP2 / 4; i += 256)
        reinterpret_cast<float4*>(As)[i] = make_float4(0.f, 0.f, 0.f, 0.f);
    __syncthreads();

    for (int i = tid; i < lim * 64; i += 256) {
        int m = i >> 6, k = i & 63;
        size_t n = (size_t)(base + m);
        float a = g_acc[n * 64 + k] + __ldg(&bf[k]);
        float hv = hh[n * 64 + k];
        As[m * KP2 + k]      = __uint_as_float(f2tf32(a));
        As[m * KP2 + 64 + k] = __uint_as_float(f2tf32(hv));
        if (write_extra) {
            oo1[n * 128 + k]      = a;
            oo1[n * 128 + 64 + k] = hv;
            oh[n * 64 + k]        = hv;
        }
    }
    __syncthreads();

    const int lane = tid & 31;
    const int w    = tid >> 5;
    const int wm = (w >> 2) * 64;        // 0 | 64
    const int wn = (w & 3) * 24;         // 0,24,48,72  (total N = 96)
    const int g = lane >> 2, t = lane & 3;
    const unsigned* Au = reinterpret_cast<const unsigned*>(As);

    float acc[4][3][4];
#pragma unroll
    for (int mf = 0; mf < 4; mf++)
#pragma unroll
        for (int nf = 0; nf < 3; nf++)
#pragma unroll
            for (int q = 0; q < 4; q++) acc[mf][nf][q] = 0.f;

#pragma unroll 1
    for (int ks = 0; ks < 16; ks++) {
        const int k0 = ks * 8;
        unsigned bfr[3][2];
#pragma unroll
        for (int nf = 0; nf < 3; nf++) {
            int nc = wn + nf * 8 + g;
            bfr[nf][0] = __float_as_uint(__ldg(&g_Wh[(k0 + t) * 96 + nc]));
            bfr[nf][1] = __float_as_uint(__ldg(&g_Wh[(k0 + 4 + t) * 96 + nc]));
        }
#pragma unroll
        for (int mf = 0; mf < 4; mf++) {
            int r0 = wm + mf * 16 + g;
            unsigned a0 = Au[r0 * KP2 + k0 + t];
            unsigned a1 = Au[(r0 + 8) * KP2 + k0 + t];
            unsigned a2 = Au[r0 * KP2 + k0 + 4 + t];
            unsigned a3 = Au[(r0 + 8) * KP2 + k0 + 4 + t];
#pragma unroll
            for (int nf = 0; nf < 3; nf++)
                mma_tf32(acc[mf][nf], a0, a1, a2, a3, bfr[nf][0], bfr[nf][1]);
        }
    }
    __syncthreads();   // all warps done reading As; safe to overwrite as hd

#pragma unroll
    for (int nf = 0; nf < 3; nf++) {
        int c = wn + nf * 8 + 2 * t;
#pragma unroll
        for (int mf = 0; mf < 4; mf++) {
            int r0 = wm + mf * 16 + g;
            *reinterpret_cast<float2*>(&hd[r0 * HD + c]) =
                make_float2(acc[mf][nf][0], acc[mf][nf][1]);
            *reinterpret_cast<float2*>(&hd[(r0 + 8) * HD + c]) =
                make_float2(acc[mf][nf][2], acc[mf][nf][3]);
        }
    }
    __syncthreads();

    const float bmv = __ldg(&bm[lane]);
    const float bsv = __ldg(&bsg[lane]);
    const float bpv = __ldg(&bp[lane]);
    for (int s = 0; s < 16; s++) {
        int row = w * 16 + s;
        int n = base + row;
        if (n >= NN) break;
        float mu = hd[row * HD + lane]      + bmv;
        float sg = hd[row * HD + 32 + lane] + bsv;
        sg = fmaxf(sg, 0.f) + log1pf(__expf(-fabsf(sg)));   // stable softplus
        float pv = hd[row * HD + 64 + lane] + bpv;
        float m = pv;
#pragma unroll
        for (int o = 16; o; o >>= 1) m = fmaxf(m, __shfl_xor_sync(0xFFFFFFFFu, m, o));
        float ex = __expf(pv - m);
        float ssum = ex;
#pragma unroll
        for (int o = 16; o; o >>= 1) ssum += __shfl_xor_sync(0xFFFFFFFFu, ssum, o);
        float pi = ex / ssum;

        ogmm[(size_t)n * 96 + lane]      = mu;
        ogmm[(size_t)n * 96 + 32 + lane] = sg;
        ogmm[(size_t)n * 96 + 64 + lane] = pi;
    }
}

// ---------------- launch ----------------
extern "C" void kernel_launch(void* const* d_in, const int* in_sizes, int n_in,
                              void* d_out, int out_size) {
    const float* x   = (const float*)d_in[0];
    const float* xh  = (const float*)d_in[1];
    const float* h   = (const float*)d_in[2];
    const int*   ei  = (const int*)d_in[3];
    const float* ew  = (const float*)d_in[4];
    const float* Win = (const float*)d_in[5];
    const float* bin = (const float*)d_in[6];
    const float* Wf  = (const float*)d_in[7];
    const float* bf  = (const float*)d_in[8];
    const float* Wm  = (const float*)d_in[9];
    const float* bm  = (const float*)d_in[10];
    const float* Wsg = (const float*)d_in[11];
    const float* bsg = (const float*)d_in[12];
    const float* Wp  = (const float*)d_in[13];
    const float* bp  = (const float*)d_in[14];
    float* out = (float*)d_out;

    int write_extra = (out_size >= NN * 96 + NN * 128 + NN * 64) ? 1 : 0;

    cudaFuncSetAttribute(k_z,    cudaFuncAttributeMaxDynamicSharedMemorySize, Z_SMEM);
    cudaFuncSetAttribute(k_head, cudaFuncAttributeMaxDynamicSharedMemorySize, HEAD_SMEM);

    k_init<<<148, 256>>>();
    k_wfold<<<128, 192>>>(Win, bin, Wf);
    k_whead<<<96, 128>>>(Wm, Wsg, Wp);
    k_deg<<<(NE + 255) / 256, 256>>>(ei, ew);
    k_z<<<(NN + 127) / 128, 256, Z_SMEM>>>(x, xh, h);
    k_scatter<<<(NE * 16) / 256, 256>>>(ei, ew);
    k_head<<<(NN + 127) / 128, 256, HEAD_SMEM>>>(h, bf, bm, bsg, bp, out, write_extra);
}

// round 12
// speedup vs baseline: 1.0460x; 1.0460x over previous
#include <cuda_runtime.h>
#include <cuda_fp16.h>
#include <math.h>
#include <stdint.h>

#define NN 100000
#define NE 1600000
#define KTOT 168          // z-GEMM K padded 161 -> 168
#define KPAD 172          // z-GEMM A smem stride
#define KP2 132           // head A smem stride
#define HD 100            // head result smem stride

// ---------------- scratch (device globals: allocation-free) ----------------
__device__ __align__(16) __half g_zf[NN * 64];   // fp16 z (forward)
__device__ __align__(16) __half g_zb[NN * 64];   // fp16 z (backward)
__device__ __align__(16) float g_acc[NN * 64];   // fp32 diffusion accumulator
__device__ float g_degf[NN];
__device__ float g_degb[NN];
__device__ __align__(16) float g_Wk[KTOT * 128]; // folded z weights (tf32), [k][c]
__device__ __align__(16) float g_bz[128];
__device__ __align__(16) float g_Wh[128 * 96];   // head weights [k][mu|sig|pi] (tf32)

// ---------------- helpers ----------------
__device__ __forceinline__ unsigned f2tf32(float v) {
    unsigned o; asm("cvt.rna.tf32.f32 %0, %1;" : "=r"(o) : "f"(v)); return o;
}

__device__ __forceinline__ void mma_tf32(float* d,
                                         unsigned a0, unsigned a1, unsigned a2, unsigned a3,
                                         unsigned b0, unsigned b1) {
    asm volatile("mma.sync.aligned.m16n8k8.row.col.f32.tf32.tf32.f32 "
                 "{%0,%1,%2,%3}, {%4,%5,%6,%7}, {%8,%9}, {%0,%1,%2,%3};"
                 : "+f"(d[0]), "+f"(d[1]), "+f"(d[2]), "+f"(d[3])
                 : "r"(a0), "r"(a1), "r"(a2), "r"(a3), "r"(b0), "r"(b1));
}

// ---------------- init accumulator + degrees ----------------
__global__ void k_init() {
    int i = blockIdx.x * blockDim.x + threadIdx.x;
    int st = gridDim.x * blockDim.x;
    float4 z = make_float4(0.f, 0.f, 0.f, 0.f);
    for (int j = i; j < NN * 16; j += st)
        reinterpret_cast<float4*>(g_acc)[j] = z;
    for (int j = i; j < NN; j += st) { g_degf[j] = 0.f; g_degb[j] = 0.f; }
}

// ---------------- fold W_filt into W_in (k-major, tf32) ----------------
__global__ void k_wfold(const float* __restrict__ Win, const float* __restrict__ bin,
                        const float* __restrict__ Wf) {
    __shared__ float wsel[64];
    int c = blockIdx.x;                 // 0..127
    if (threadIdx.x < 64) {
        int j = threadIdx.x;
        wsel[j] = (c < 64) ? Wf[j * 64 + c] : Wf[(64 + j) * 64 + (c - 64)];
    }
    __syncthreads();
    int k = threadIdx.x;
    if (k < KTOT) {
        float a = 0.f;
        if (k < 161) {
#pragma unroll 8
            for (int j = 0; j < 64; j++) a += Win[k * 64 + j] * wsel[j];
        }
        g_Wk[k * 128 + c] = __uint_as_float(f2tf32(a));
    }
    if (threadIdx.x == 0) {
        float b = 0.f;
        for (int j = 0; j < 64; j++) b += bin[j] * wsel[j];
        g_bz[c] = b;
    }
}

// ---------------- pack head weights [Wm|Ws|Wp] -> g_Wh[k][96] (tf32) ----------------
__global__ void k_whead(const float* __restrict__ Wm, const float* __restrict__ Wsg,
                        const float* __restrict__ Wp) {
    int c = blockIdx.x;                 // 0..95
    int j = threadIdx.x;                // 0..127
    float v = (c < 32) ? Wm[j * 32 + c]
            : (c < 64) ? Wsg[j * 32 + (c - 32)]
                       : Wp[j * 32 + (c - 64)];
    g_Wh[j * 96 + c] = __uint_as_float(f2tf32(v));
}

// ---------------- weighted degrees ----------------
__global__ void k_deg(const int* __restrict__ ei, const float* __restrict__ ew) {
    int e = blockIdx.x * blockDim.x + threadIdx.x;
    if (e >= NE) return;
    int s = ei[e], t = ei[NE + e];
    float w = ew[e];
    if (s != t) {
        atomicAdd(&g_degf[t], w);
        atomicAdd(&g_degb[s], w);
    }
}

// ---------------- z = A @ Wc + bz  (tf32 MMA, 64-row tiles, fp16 output) ----------------
#define ZM 64
#define Z_SMEM (ZM * KPAD * 4)

__global__ __launch_bounds__(256) void k_z(const float* __restrict__ x,
                                           const float* __restrict__ xh,
                                           const float* __restrict__ hh) {
    extern __shared__ float As[];       // [ZM][KPAD]
    const int tid = threadIdx.x;
    const int base = blockIdx.x * ZM;

    for (int i = tid; i < ZM * KPAD / 4; i += 256)
        reinterpret_cast<float4*>(As)[i] = make_float4(0.f, 0.f, 0.f, 0.f);
    __syncthreads();

    {
        int lim = min(ZM, NN - base);
        if (tid < lim) As[tid * KPAD] = __uint_as_float(f2tf32(x[base + tid]));
        for (int i = tid; i < lim * 96; i += 256) {
            int m = i / 96, k = i - m * 96;
            As[m * KPAD + 1 + k] = __uint_as_float(f2tf32(xh[(size_t)(base + m) * 96 + k]));
        }
        for (int i = tid; i < lim * 64; i += 256) {
            int m = i >> 6, k = i & 63;
            As[m * KPAD + 97 + k] = __uint_as_float(f2tf32(hh[(size_t)(base + m) * 64 + k]));
        }
    }
    __syncthreads();

    const int lane = tid & 31;
    const int w    = tid >> 5;
    const int wm = (w >> 2) * 32;       // 0 | 32
    const int wn = (w & 3) * 32;        // 0,32,64,96
    const int g = lane >> 2, t = lane & 3;
    const unsigned* Au = reinterpret_cast<const unsigned*>(As);

    float acc[2][4][4];
#pragma unroll
    for (int mf = 0; mf < 2; mf++)
#pragma unroll
        for (int nf = 0; nf < 4; nf++)
#pragma unroll
            for (int q = 0; q < 4; q++) acc[mf][nf][q] = 0.f;

#pragma unroll 1
    for (int ks = 0; ks < 21; ks++) {
        const int k0 = ks * 8;
        unsigned bfr[4][2];
#pragma unroll
        for (int nf = 0; nf < 4; nf++) {
            int nc = wn + nf * 8 + g;
            bfr[nf][0] = __float_as_uint(__ldg(&g_Wk[(k0 + t) * 128 + nc]));
            bfr[nf][1] = __float_as_uint(__ldg(&g_Wk[(k0 + 4 + t) * 128 + nc]));
        }
#pragma unroll
        for (int mf = 0; mf < 2; mf++) {
            int r0 = wm + mf * 16 + g;
            unsigned a0 = Au[r0 * KPAD + k0 + t];
            unsigned a1 = Au[(r0 + 8) * KPAD + k0 + t];
            unsigned a2 = Au[r0 * KPAD + k0 + 4 + t];
            unsigned a3 = Au[(r0 + 8) * KPAD + k0 + 4 + t];
#pragma unroll
            for (int nf = 0; nf < 4; nf++)
                mma_tf32(acc[mf][nf], a0, a1, a2, a3, bfr[nf][0], bfr[nf][1]);
        }
    }

    // epilogue: add bias, convert to fp16, route cols<64 -> zf, else zb
#pragma unroll
    for (int nf = 0; nf < 4; nf++) {
        int c = wn + nf * 8 + 2 * t;
        float bi0 = g_bz[c], bi1 = g_bz[c + 1];
        __half* dst = (c < 64) ? g_zf : g_zb;
        int cd = (c < 64) ? c : c - 64;
#pragma unroll
        for (int mf = 0; mf < 2; mf++) {
            int m0 = base + wm + mf * 16 + g;
            if (m0 < NN)
                *reinterpret_cast<__half2*>(&dst[(size_t)m0 * 64 + cd]) =
                    __floats2half2_rn(acc[mf][nf][0] + bi0, acc[mf][nf][1] + bi1);
            int m1 = m0 + 8;
            if (m1 < NN)
                *reinterpret_cast<__half2*>(&dst[(size_t)m1 * 64 + cd]) =
                    __floats2half2_rn(acc[mf][nf][2] + bi0, acc[mf][nf][3] + bi1);
        }
    }
}

// ---------------- scatter: fp16 z loads, fp32 REDs ----------------
__device__ __forceinline__ void red4(float* p, float a, float b, float c, float d) {
    asm volatile("red.global.add.v4.f32 [%0], {%1, %2, %3, %4};"
                 :: "l"(p), "f"(a), "f"(b), "f"(c), "f"(d) : "memory");
}

__global__ __launch_bounds__(256) void k_scatter(const int* __restrict__ ei,
                                                 const float* __restrict__ ew) {
    const int lane = threadIdx.x & 31;
    const int sub  = lane & 15;          // position within 16-lane edge group
    const unsigned warp_id = blockIdx.x * 8u + (threadIdx.x >> 5);
    const unsigned e = warp_id * 2u + (unsigned)(lane >> 4);
    if (e >= NE) return;

    int s = 0, t = 0;
    float wf = 0.f, wb = 0.f;
    if (sub == 0) {                      // lanes 0 and 16 do the scalar work
        s = __ldg(&ei[e]);
        t = __ldg(&ei[NE + e]);
        float w = __ldg(&ew[e]);
        if (s == t) w = 0.f;
        float df = __ldg(&g_degf[t]);
        float db = __ldg(&g_degb[s]);
        wf = (df > 0.f) ? w / df : 0.f;
        wb = (db > 0.f) ? w / db : 0.f;
    }
    const int srcl = lane & 16;          // broadcast source within each half
    s  = __shfl_sync(0xFFFFFFFFu, s,  srcl);
    t  = __shfl_sync(0xFFFFFFFFu, t,  srcl);
    wf = __shfl_sync(0xFFFFFFFFu, wf, srcl);
    wb = __shfl_sync(0xFFFFFFFFu, wb, srcl);

    {
        uint2 u = *reinterpret_cast<const uint2*>(g_zf + (size_t)s * 64 + 4 * sub);
        float2 f0 = __half22float2(*reinterpret_cast<const __half2*>(&u.x));
        float2 f1 = __half22float2(*reinterpret_cast<const __half2*>(&u.y));
        red4(g_acc + (size_t)t * 64 + 4 * sub, wf * f0.x, wf * f0.y, wf * f1.x, wf * f1.y);
    }
    {
        uint2 u = *reinterpret_cast<const uint2*>(g_zb + (size_t)t * 64 + 4 * sub);
        float2 f0 = __half22float2(*reinterpret_cast<const __half2*>(&u.x));
        float2 f1 = __half22float2(*reinterpret_cast<const __half2*>(&u.y));
        red4(g_acc + (size_t)s * 64 + 4 * sub, wb * f0.x, wb * f0.y, wb * f1.x, wb * f1.y);
    }
}

// ---------------- head: tf32 MMA GMM heads + outputs ----------------
#define HEAD_SMEM (128 * KP2 * 4)

__global__ __launch_bounds__(256) void k_head(const float* __restrict__ hh,
                                              const float* __restrict__ bf,
                                              const float* __restrict__ bm,
                                              const float* __restrict__ bsg,
                                              const float* __restrict__ bp,
                                              float* __restrict__ out, int write_extra) {
    extern __shared__ float sms[];
    float* As = sms;                     // [128][KP2], later aliased as hd [128][HD]
    float* hd = sms;

    const int tid = threadIdx.x;
    const int base = blockIdx.x * 128;
    const int lim = min(128, NN - base);

    float* ogmm = out;
    float* oo1  = out + (size_t)NN * 96;
    float* oh   = out + (size_t)NN * 96 + (size_t)NN * 128;

    for (int i = tid; i < 128 * KP2 / 4; i += 256)
        reinterpret_cast<float4*>(As)[i] = make_float4(0.f, 0.f, 0.f, 0.f);
    __syncthreads();

    for (int i = tid; i < lim * 64; i += 256) {
        int m = i >> 6, k = i & 63;
        size_t n = (size_t)(base + m);
        float a = g_acc[n * 64 + k] + __ldg(&bf[k]);
        float hv = hh[n * 64 + k];
        As[m * KP2 + k]      = __uint_as_float(f2tf32(a));
        As[m * KP2 + 64 + k] = __uint_as_float(f2tf32(hv));
        if (write_extra) {
            oo1[n * 128 + k]      = a;
            oo1[n * 128 + 64 + k] = hv;
            oh[n * 64 + k]        = hv;
        }
    }
    __syncthreads();

    const int lane = tid & 31;
    const int w    = tid >> 5;
    const int wm = (w >> 2) * 64;        // 0 | 64
    const int wn = (w & 3) * 24;         // 0,24,48,72  (total N = 96)
    const int g = lane >> 2, t = lane & 3;
    const unsigned* Au = reinterpret_cast<const unsigned*>(As);

    float acc[4][3][4];
#pragma unroll
    for (int mf = 0; mf < 4; mf++)
#pragma unroll
        for (int nf = 0; nf < 3; nf++)
#pragma unroll
            for (int q = 0; q < 4; q++) acc[mf][nf][q] = 0.f;

#pragma unroll 1
    for (int ks = 0; ks < 16; ks++) {
        const int k0 = ks * 8;
        unsigned bfr[3][2];
#pragma unroll
        for (int nf = 0; nf < 3; nf++) {
            int nc = wn + nf * 8 + g;
            bfr[nf][0] = __float_as_uint(__ldg(&g_Wh[(k0 + t) * 96 + nc]));
            bfr[nf][1] = __float_as_uint(__ldg(&g_Wh[(k0 + 4 + t) * 96 + nc]));
        }
#pragma unroll
        for (int mf = 0; mf < 4; mf++) {
            int r0 = wm + mf * 16 + g;
            unsigned a0 = Au[r0 * KP2 + k0 + t];
            unsigned a1 = Au[(r0 + 8) * KP2 + k0 + t];
            unsigned a2 = Au[r0 * KP2 + k0 + 4 + t];
            unsigned a3 = Au[(r0 + 8) * KP2 + k0 + 4 + t];
#pragma unroll
            for (int nf = 0; nf < 3; nf++)
                mma_tf32(acc[mf][nf], a0, a1, a2, a3, bfr[nf][0], bfr[nf][1]);
        }
    }
    __syncthreads();   // all warps done reading As; safe to overwrite as hd

#pragma unroll
    for (int nf = 0; nf < 3; nf++) {
        int c = wn + nf * 8 + 2 * t;
#pragma unroll
        for (int mf = 0; mf < 4; mf++) {
            int r0 = wm + mf * 16 + g;
            *reinterpret_cast<float2*>(&hd[r0 * HD + c]) =
                make_float2(acc[mf][nf][0], acc[mf][nf][1]);
            *reinterpret_cast<float2*>(&hd[(r0 + 8) * HD + c]) =
                make_float2(acc[mf][nf][2], acc[mf][nf][3]);
        }
    }
    __syncthreads();

    const float bmv = __ldg(&bm[lane]);
    const float bsv = __ldg(&bsg[lane]);
    const float bpv = __ldg(&bp[lane]);
    for (int s = 0; s < 16; s++) {
        int row = w * 16 + s;
        int n = base + row;
        if (n >= NN) break;
        float mu = hd[row * HD + lane]      + bmv;
        float sg = hd[row * HD + 32 + lane] + bsv;
        sg = fmaxf(sg, 0.f) + log1pf(__expf(-fabsf(sg)));   // stable softplus
        float pv = hd[row * HD + 64 + lane] + bpv;
        float m = pv;
#pragma unroll
        for (int o = 16; o; o >>= 1) m = fmaxf(m, __shfl_xor_sync(0xFFFFFFFFu, m, o));
        float ex = __expf(pv - m);
        float ssum = ex;
#pragma unroll
        for (int o = 16; o; o >>= 1) ssum += __shfl_xor_sync(0xFFFFFFFFu, ssum, o);
        float pi = ex / ssum;

        ogmm[(size_t)n * 96 + lane]      = mu;
        ogmm[(size_t)n * 96 + 32 + lane] = sg;
        ogmm[(size_t)n * 96 + 64 + lane] = pi;
    }
}

// ---------------- launch ----------------
extern "C" void kernel_launch(void* const* d_in, const int* in_sizes, int n_in,
                              void* d_out, int out_size) {
    const float* x   = (const float*)d_in[0];
    const float* xh  = (const float*)d_in[1];
    const float* h   = (const float*)d_in[2];
    const int*   ei  = (const int*)d_in[3];
    const float* ew  = (const float*)d_in[4];
    const float* Win = (const float*)d_in[5];
    const float* bin = (const float*)d_in[6];
    const float* Wf  = (const float*)d_in[7];
    const float* bf  = (const float*)d_in[8];
    const float* Wm  = (const float*)d_in[9];
    const float* bm  = (const float*)d_in[10];
    const float* Wsg = (const float*)d_in[11];
    const float* bsg = (const float*)d_in[12];
    const float* Wp  = (const float*)d_in[13];
    const float* bp  = (const float*)d_in[14];
    float* out = (float*)d_out;

    int write_extra = (out_size >= NN * 96 + NN * 128 + NN * 64) ? 1 : 0;

    cudaFuncSetAttribute(k_z,    cudaFuncAttributeMaxDynamicSharedMemorySize, Z_SMEM);
    cudaFuncSetAttribute(k_head, cudaFuncAttributeMaxDynamicSharedMemorySize, HEAD_SMEM);

    k_init<<<148, 256>>>();
    k_wfold<<<128, 192>>>(Win, bin, Wf);
    k_whead<<<96, 128>>>(Wm, Wsg, Wp);
    k_deg<<<(NE + 255) / 256, 256>>>(ei, ew);
    k_z<<<(NN + ZM - 1) / ZM, 256, Z_SMEM>>>(x, xh, h);
    k_scatter<<<(NE * 16) / 256, 256>>>(ei, ew);
    k_head<<<(NN + 127) / 128, 256, HEAD_SMEM>>>(h, bf, bm, bsg, bp, out, write_extra);
}